// round 5
// baseline (speedup 1.0000x reference)
#include <cuda_runtime.h>
#include <math.h>
#include <stdint.h>

// Problem constants
#define NB   64      // num_groups (B)
#define NG   32      // group_size (G)
#define ND   2000    // output dim (D)
#define NM   16      // m_samples
#define NE   16      // noise dim
#define NDIN 256
#define KTOT 272     // DIN + E
#define EPSC 1e-12f

// ---------------- scratch (device globals; referenced directly by kernels) ----------------
__device__ float g_Xs[NB * NDIN];          // sum over g of x            [64,256]
__device__ float g_Ns[NB * NM * NE];       // sum over g of noise_loss   [1024,16]
__device__ float g_P [NB * NM * ND];       // loss-path predictions      [1024,2000]
__device__ float g_Y [NB * NG * ND];       // x_pred -> IPF y (in place) [2048,2000]
__device__ float g_lossPart[NB];

// ---------------- stage 1: group reductions ----------------
__global__ void k_reduce(const float* __restrict__ x, const float* __restrict__ nl) {
    int i = blockIdx.x * 256 + threadIdx.x;
    if (i < NB * NDIN) {
        int b = i >> 8, k = i & 255;
        float s = 0.f;
        #pragma unroll 8
        for (int g = 0; g < NG; g++) s += x[(size_t)(b * NG + g) * NDIN + k];
        g_Xs[i] = s;
    } else {
        int j = i - NB * NDIN;             // j < 1024*16
        int row = j >> 4, e = j & 15;      // row = b*16 + m
        int b = row >> 4, m = row & 15;
        float s = 0.f;
        #pragma unroll 8
        for (int g = 0; g < NG; g++) s += nl[(size_t)((b * NG + g) * NM + m) * NE + e];
        g_Ns[j] = s;
    }
}

// ---------------- stage 2: GEMMs (fp32 SIMT, 128x128x16 tile, 8x8/thread) ----------------
// MODE 0: M=1024, A(r,k<256)=g_Xs[r>>4][k], A(r,k>=256)=g_Ns[r][k-256], out = acc + 32*bias -> g_P
// MODE 1: M=2048, A(r,k<256)=x[r][k],       A(r,k>=256)=noise_sample[r][k-256],
//         out = softplus(acc + bias) -> g_Y
template <int MODE>
__global__ void k_gemm(const float* __restrict__ src0, const float* __restrict__ src1,
                       const float* __restrict__ W, const float* __restrict__ bias) {
    __shared__ float As[16 * 128];  // [k][m]
    __shared__ float Bs[16 * 128];  // [k][n]
    const int tid = threadIdx.x;                  // 256 threads
    const int bn = blockIdx.x, bm = blockIdx.y;
    const int tr = tid >> 4, tc = tid & 15;

    const float* a0 = (MODE == 0) ? g_Xs : src0;
    const float* a1 = (MODE == 0) ? g_Ns : src1;
    float* out = (MODE == 0) ? g_P : g_Y;

    float acc[8][8];
    #pragma unroll
    for (int i = 0; i < 8; i++)
        #pragma unroll
        for (int j = 0; j < 8; j++) acc[i][j] = 0.f;

    for (int kt = 0; kt < 17; kt++) {             // 272 = 17 * 16
        // A tile: 128 rows x 16 k (as 512 float4)
        #pragma unroll
        for (int i = 0; i < 2; i++) {
            int idx = tid + i * 256;
            int kq = idx >> 7;                    // 0..3 (float4 along k)
            int row = idx & 127;
            int rowG = bm * 128 + row;
            float4 v;
            if (kt < 16) {
                int col = kt * 16 + kq * 4;
                int r0 = (MODE == 0) ? (rowG >> 4) : rowG;
                v = *(const float4*)(a0 + (size_t)r0 * NDIN + col);
            } else {
                v = *(const float4*)(a1 + (size_t)rowG * NE + kq * 4);
            }
            As[(kq * 4 + 0) * 128 + row] = v.x;
            As[(kq * 4 + 1) * 128 + row] = v.y;
            As[(kq * 4 + 2) * 128 + row] = v.z;
            As[(kq * 4 + 3) * 128 + row] = v.w;
        }
        // B tile: 16 k x 128 n
        #pragma unroll
        for (int i = 0; i < 2; i++) {
            int idx = tid + i * 256;
            int kr = idx >> 5, cq = idx & 31;
            int d = bn * 128 + cq * 4;
            float4 v = make_float4(0.f, 0.f, 0.f, 0.f);
            if (d < ND) v = *(const float4*)(W + (size_t)(kt * 16 + kr) * ND + d);
            *(float4*)(Bs + kr * 128 + cq * 4) = v;
        }
        __syncthreads();
        #pragma unroll
        for (int kk = 0; kk < 16; kk++) {
            float a[8], bv[8];
            *(float4*)(a)      = *(const float4*)(As + kk * 128 + tr * 8);
            *(float4*)(a + 4)  = *(const float4*)(As + kk * 128 + tr * 8 + 4);
            *(float4*)(bv)     = *(const float4*)(Bs + kk * 128 + tc * 8);
            *(float4*)(bv + 4) = *(const float4*)(Bs + kk * 128 + tc * 8 + 4);
            #pragma unroll
            for (int ii = 0; ii < 8; ii++)
                #pragma unroll
                for (int jj = 0; jj < 8; jj++)
                    acc[ii][jj] = fmaf(a[ii], bv[jj], acc[ii][jj]);
        }
        __syncthreads();
    }
    // epilogue
    #pragma unroll
    for (int ii = 0; ii < 8; ii++) {
        int row = bm * 128 + tr * 8 + ii;
        #pragma unroll
        for (int jj = 0; jj < 8; jj++) {
            int col = bn * 128 + tc * 8 + jj;
            if (col < ND) {
                float r;
                if (MODE == 0) {
                    r = acc[ii][jj] + 32.f * bias[col];
                } else {
                    float z = acc[ii][jj] + bias[col];
                    // softplus = max(z,0) + log1p(exp(-|z|))
                    r = fmaxf(z, 0.f) + log1pf(expf(-fabsf(z)));
                }
                out[(size_t)row * ND + col] = r;
            }
        }
    }
}

// ---------------- stage 3: loss (one CTA per b; thread = (m,n) pair) ----------------
__global__ void k_loss(const float* __restrict__ target) {
    const int b = blockIdx.x;
    const int tid = threadIdx.x;        // 256
    const int m = tid >> 4, n = tid & 15;
    __shared__ float sP[16 * 129];
    __shared__ float sT[128];
    __shared__ float s_sq[16], s_td[16], s_w[8];

    float inn = 0.f, td = 0.f;
    for (int ch = 0; ch < 16; ch++) {   // 16*128 = 2048 >= 2000
        int dBase = ch * 128;
        #pragma unroll
        for (int i = 0; i < 8; i++) {
            int idx = tid + i * 256;
            int mm = idx >> 7, dd = idx & 127;
            int d = dBase + dd;
            sP[mm * 129 + dd] = (d < ND) ? g_P[(size_t)(b * NM + mm) * ND + d] : 0.f;
        }
        if (tid < 128) sT[tid] = (dBase + tid < ND) ? target[(size_t)b * ND + dBase + tid] : 0.f;
        __syncthreads();
        #pragma unroll 4
        for (int dd = 0; dd < 128; dd++) {
            float pm = sP[m * 129 + dd], pn = sP[n * 129 + dd];
            inn = fmaf(pm, pn, inn);
            if (m == n) { float df = pm - sT[dd]; td = fmaf(df, df, td); }
        }
        __syncthreads();
    }
    if (m == n) { s_sq[m] = inn; s_td[m] = td; }
    __syncthreads();
    float pd = 0.f;
    if (m != n) pd = sqrtf(fmaxf(s_sq[m] + s_sq[n] - 2.f * inn, 1e-6f));
    #pragma unroll
    for (int o = 16; o; o >>= 1) pd += __shfl_xor_sync(0xffffffffu, pd, o);
    if ((tid & 31) == 0) s_w[tid >> 5] = pd;
    __syncthreads();
    if (tid == 0) {
        float tot = 0.f;
        for (int w = 0; w < 8; w++) tot += s_w[w];
        float tc = 0.f;
        for (int mm = 0; mm < 16; mm++) tc += sqrtf(s_td[mm]);
        g_lossPart[b] = tc / 16.f - 0.5f * (tot / 240.f);   // LAM/2 = 0.5, M*(M-1)=240
    }
}

__global__ void k_loss_final(float* __restrict__ out, int off) {
    if (off >= 1 && threadIdx.x == 0 && blockIdx.x == 0) {
        float s = 0.f;
        for (int i = 0; i < NB; i++) s += g_lossPart[i];   // fixed order -> deterministic
        out[0] = s / (float)NB;
    }
}

// ---------------- stage 4: IPF (one CTA per b; 60 iterations in-kernel) ----------------
__global__ void k_ipf(const int* __restrict__ ts) {
    const int b = blockIdx.x;
    const int tid = threadIdx.x;        // 512
    const int lane = tid & 31, warp = tid >> 5;
    float* y = g_Y + (size_t)b * NG * ND;
    const int* tsb = ts + (size_t)b * ND;
    __shared__ float s_red[16 * 32];    // [warp][g]
    __shared__ float s_R[32];
    __shared__ float s_rowfac[32];

    float C0[4], colsum[4];
    #pragma unroll
    for (int c = 0; c < 4; c++) {
        int d = tid + c * 512;
        C0[c] = (d < ND) ? fmaxf((float)__ldg(&tsb[d]), 0.f) : 0.f;
        colsum[c] = 0.f;
    }

    // init pass: col sums + row anchors R (pre-smoothing, as in reference)
    for (int g = 0; g < NG; g++) {
        float rp = 0.f;
        #pragma unroll
        for (int c = 0; c < 4; c++) {
            int d = tid + c * 512;
            if (d < ND) { float v = y[g * ND + d]; colsum[c] += v; rp += v; }
        }
        #pragma unroll
        for (int o = 16; o; o >>= 1) rp += __shfl_xor_sync(0xffffffffu, rp, o);
        if (lane == 0) s_red[warp * 32 + g] = rp;
    }
    __syncthreads();
    if (tid < 32) {
        float s = 0.f;
        #pragma unroll
        for (int w = 0; w < 16; w++) s += s_red[w * 32 + tid];
        s_R[tid] = s;
    }
    __syncthreads();

    // col_zero smoothing (dead in practice — softplus > 0 — kept for exactness)
    #pragma unroll
    for (int c = 0; c < 4; c++) {
        int d = tid + c * 512;
        if (d < ND && colsum[c] <= 0.f && C0[c] > 0.f) {
            for (int g = 0; g < NG; g++) y[g * ND + d] += 1e-8f;
            colsum[c] = 32.f * 1e-8f;
        }
    }

    for (int it = 0; it < 60; it++) {
        float cf[4];
        #pragma unroll
        for (int c = 0; c < 4; c++)
            cf[c] = fminf(fmaxf(C0[c] / fmaxf(colsum[c], EPSC), 0.75f), 1.25f);
        // pass A: apply col factor, accumulate row partials
        for (int g = 0; g < NG; g++) {
            float rp = 0.f;
            #pragma unroll
            for (int c = 0; c < 4; c++) {
                int d = tid + c * 512;
                if (d < ND) { float v = y[g * ND + d] * cf[c]; y[g * ND + d] = v; rp += v; }
            }
            #pragma unroll
            for (int o = 16; o; o >>= 1) rp += __shfl_xor_sync(0xffffffffu, rp, o);
            if (lane == 0) s_red[warp * 32 + g] = rp;
        }
        __syncthreads();
        if (tid < 32) {
            float s = 0.f;
            #pragma unroll
            for (int w = 0; w < 16; w++) s += s_red[w * 32 + tid];
            s_rowfac[tid] = fminf(fmaxf(s_R[tid] / fmaxf(s, EPSC), 0.75f), 1.25f);
        }
        __syncthreads();
        // pass B: apply row factor, accumulate next col sums
        #pragma unroll
        for (int c = 0; c < 4; c++) colsum[c] = 0.f;
        for (int g = 0; g < NG; g++) {
            float rf = s_rowfac[g];
            #pragma unroll
            for (int c = 0; c < 4; c++) {
                int d = tid + c * 512;
                if (d < ND) { float v = y[g * ND + d] * rf; y[g * ND + d] = v; colsum[c] += v; }
            }
        }
    }
    // final column normalization (no trust clamp)
    #pragma unroll
    for (int c = 0; c < 4; c++) {
        int d = tid + c * 512;
        if (d < ND) {
            float f = C0[c] / fmaxf(colsum[c], EPSC);
            for (int g = 0; g < NG; g++) y[g * ND + d] *= f;
        }
    }
}

// ---------------- stage 5: exact integerization (warp per (b,d)) ----------------
__global__ void k_round(const int* __restrict__ ts, float* __restrict__ out, int off) {
    const unsigned FULL = 0xffffffffu;
    int wId = blockIdx.x * (blockDim.x >> 5) + (threadIdx.x >> 5);
    int lane = threadIdx.x & 31;
    if (wId >= NB * ND) return;
    int b = wId / ND, d = wId - b * ND;

    float v = g_Y[(size_t)(b * NG + lane) * ND + d];
    v = fmaxf(v, 0.f);
    float xf = floorf(v);
    int yi = (int)xf;
    float fr = v - xf;
    int t = ts[(size_t)b * ND + d];

    int s = __reduce_add_sync(FULL, yi);
    int need = t - s;
    int pos = need > 0 ? need : 0;
    int q = pos >> 5;
    yi += q;
    int r = pos - (q << 5);
    // descending stable rank of fr (ties -> smaller index first)
    int cnt = 0;
    #pragma unroll
    for (int k = 1; k < 32; k++) {
        int j = (lane + k) & 31;
        float o = __shfl_sync(FULL, fr, j);
        cnt += (o > fr) || (o == fr && j < lane);
    }
    if (cnt < r) yi += 1;

    int s2 = __reduce_add_sync(FULL, yi);
    int need2 = t - s2;
    int neg = need2 < 0 ? -need2 : 0;
    neg = neg < s2 ? neg : s2;
    int q2 = neg >> 5;
    int yb = yi;
    yi -= q2; if (yi < 0) yi = 0;
    int removed = __reduce_add_sync(FULL, yb - yi);
    int r2 = neg - removed;
    float fm = (yi > 0) ? fr : __int_as_float(0x7f800000);  // +inf
    int cnt2 = 0;
    #pragma unroll
    for (int k = 1; k < 32; k++) {
        int j = (lane + k) & 31;
        float o = __shfl_sync(FULL, fm, j);
        cnt2 += (o < fm) || (o == fm && j < lane);
    }
    if (cnt2 < r2) yi -= 1;
    if (yi < 0) yi = 0;

    out[(size_t)off + (size_t)(b * NG + lane) * ND + d] = (float)yi;
}

// ---------------- launch (pure kernel launches; no runtime API calls) ----------------
extern "C" void kernel_launch(void* const* d_in, const int* in_sizes, int n_in,
                              void* d_out, int out_size) {
    const float* x      = (const float*)d_in[0];   // [2048,256]
    const float* target = (const float*)d_in[1];   // [64,2000]
    const int*   tsum   = (const int*)  d_in[2];   // [64,2000]
    const float* W      = (const float*)d_in[3];   // [272,2000]
    const float* bias   = (const float*)d_in[4];   // [2000]
    const float* nl     = (const float*)d_in[5];   // [32768,16]
    const float* ns     = (const float*)d_in[6];   // [2048,16]
    float* out = (float*)d_out;

    int off = out_size - NB * NG * ND;             // expected 1 (loss scalar first)
    if (off < 0) off = 0;

    // 1) group reductions (32768 threads)
    k_reduce<<<128, 256>>>(x, nl);
    // 2) loss-path GEMM: g_P[1024,2000]
    k_gemm<0><<<dim3(16, 8), 256>>>(nullptr, nullptr, W, bias);
    // 3) sample GEMM with softplus: g_Y[2048,2000]
    k_gemm<1><<<dim3(16, 16), 256>>>(x, ns, W, bias);
    // 4) loss per-b, then deterministic final sum
    k_loss<<<NB, 256>>>(target);
    k_loss_final<<<1, 32>>>(out, off);
    // 5) IPF, 60 iterations in-kernel (one CTA per b)
    k_ipf<<<NB, 512>>>(tsum);
    // 6) exact integer rounding, write y to d_out
    k_round<<<(NB * ND) / 8, 256>>>(tsum, out, off);
}

// round 7
// speedup vs baseline: 3.1298x; 3.1298x over previous
#include <cuda_runtime.h>
#include <math.h>
#include <stdint.h>

// Problem constants
#define NB   64      // num_groups (B)
#define NG   32      // group_size (G)
#define ND   2000    // output dim (D)
#define NM   16      // m_samples
#define NE   16      // noise dim
#define NDIN 256
#define KTOT 272     // DIN + E
#define EPSC 1e-12f

// ---------------- scratch (device globals; referenced directly by kernels) ----------------
__device__ __align__(16) float g_Xs[NB * NDIN];    // sum over g of x            [64,256]
__device__ __align__(16) float g_Ns[NB * NM * NE]; // sum over g of noise_loss   [1024,16]
__device__ __align__(16) float g_P [NB * NM * ND]; // loss-path predictions      [1024,2000]
__device__ __align__(16) float g_Y [NB * NG * ND]; // x_pred -> IPF y (in place) [2048,2000]
__device__ float g_lossInn[NB * 4 * 256];
__device__ float g_lossTd [NB * 4 * 16];
__device__ float g_lossPart[NB];

__device__ __forceinline__ uint32_t smem_u32(const void* p) {
    uint32_t a;
    asm("{ .reg .u64 t; cvta.to.shared.u64 t, %1; cvt.u32.u64 %0, t; }" : "=r"(a) : "l"(p));
    return a;
}
__device__ __forceinline__ uint32_t mapa_u32(uint32_t addr, uint32_t rank) {
    uint32_t r;
    asm("mapa.shared::cluster.u32 %0, %1, %2;" : "=r"(r) : "r"(addr), "r"(rank));
    return r;
}

// ---------------- stage 1: group reductions ----------------
__global__ void k_reduce(const float* __restrict__ x, const float* __restrict__ nl) {
    int i = blockIdx.x * 256 + threadIdx.x;
    if (i < NB * NDIN) {
        int b = i >> 8, k = i & 255;
        float s = 0.f;
        #pragma unroll 8
        for (int g = 0; g < NG; g++) s += x[(size_t)(b * NG + g) * NDIN + k];
        g_Xs[i] = s;
    } else {
        int j = i - NB * NDIN;             // j < 1024*16
        int row = j >> 4, e = j & 15;      // row = b*16 + m
        int b = row >> 4, m = row & 15;
        float s = 0.f;
        #pragma unroll 8
        for (int g = 0; g < NG; g++) s += nl[(size_t)((b * NG + g) * NM + m) * NE + e];
        g_Ns[j] = s;
    }
}

// ---------------- stage 2: GEMMs (fp32 SIMT, 128x128x16 tile, 8x8/thread, 2-stage pipeline) ----------------
template <int MODE>
__global__ void __launch_bounds__(256, 2)
k_gemm(const float* __restrict__ src0, const float* __restrict__ src1,
       const float* __restrict__ W, const float* __restrict__ bias) {
    __shared__ float As[2][16 * 128];  // [buf][k][m]
    __shared__ float Bs[2][16 * 128];  // [buf][k][n]
    const int tid = threadIdx.x;                  // 256 threads
    const int bn = blockIdx.x, bm = blockIdx.y;
    const int tr = tid >> 4, tc = tid & 15;

    const float* a0 = (MODE == 0) ? g_Xs : src0;
    const float* a1 = (MODE == 0) ? g_Ns : src1;
    float* out = (MODE == 0) ? g_P : g_Y;

    auto loadA = [&](int kt, int i) -> float4 {
        int idx = tid + i * 256;
        int kq = idx >> 7, row = idx & 127;
        int rowG = bm * 128 + row;
        if (kt < 16) {
            int r0 = (MODE == 0) ? (rowG >> 4) : rowG;
            return *(const float4*)(a0 + (size_t)r0 * NDIN + kt * 16 + kq * 4);
        }
        return *(const float4*)(a1 + (size_t)rowG * NE + kq * 4);
    };
    auto loadB = [&](int kt, int i) -> float4 {
        int idx = tid + i * 256;
        int kr = idx >> 5, cq = idx & 31;
        int d = bn * 128 + cq * 4;
        if (d < ND) return *(const float4*)(W + (size_t)(kt * 16 + kr) * ND + d);
        return make_float4(0.f, 0.f, 0.f, 0.f);
    };
    auto storeA = [&](int buf, int i, float4 v) {
        int idx = tid + i * 256;
        int kq = idx >> 7, row = idx & 127;
        As[buf][(kq * 4 + 0) * 128 + row] = v.x;
        As[buf][(kq * 4 + 1) * 128 + row] = v.y;
        As[buf][(kq * 4 + 2) * 128 + row] = v.z;
        As[buf][(kq * 4 + 3) * 128 + row] = v.w;
    };
    auto storeB = [&](int buf, int i, float4 v) {
        int idx = tid + i * 256;
        int kr = idx >> 5, cq = idx & 31;
        *(float4*)(&Bs[buf][kr * 128 + cq * 4]) = v;
    };

    float acc[8][8];
    #pragma unroll
    for (int i = 0; i < 8; i++)
        #pragma unroll
        for (int j = 0; j < 8; j++) acc[i][j] = 0.f;

    // prologue: stage tile 0
    float4 pa0 = loadA(0, 0), pa1 = loadA(0, 1);
    float4 pb0 = loadB(0, 0), pb1 = loadB(0, 1);
    storeA(0, 0, pa0); storeA(0, 1, pa1);
    storeB(0, 0, pb0); storeB(0, 1, pb1);
    __syncthreads();

    for (int kt = 0; kt < 17; kt++) {             // 272 = 17 * 16
        int cur = kt & 1;
        if (kt < 16) {                            // prefetch next tile into regs
            pa0 = loadA(kt + 1, 0); pa1 = loadA(kt + 1, 1);
            pb0 = loadB(kt + 1, 0); pb1 = loadB(kt + 1, 1);
        }
        const float* Ab = As[cur];
        const float* Bb = Bs[cur];
        #pragma unroll
        for (int kk = 0; kk < 16; kk++) {
            float a[8], bv[8];
            *(float4*)(a)      = *(const float4*)(Ab + kk * 128 + tr * 8);
            *(float4*)(a + 4)  = *(const float4*)(Ab + kk * 128 + tr * 8 + 4);
            *(float4*)(bv)     = *(const float4*)(Bb + kk * 128 + tc * 8);
            *(float4*)(bv + 4) = *(const float4*)(Bb + kk * 128 + tc * 8 + 4);
            #pragma unroll
            for (int ii = 0; ii < 8; ii++)
                #pragma unroll
                for (int jj = 0; jj < 8; jj++)
                    acc[ii][jj] = fmaf(a[ii], bv[jj], acc[ii][jj]);
        }
        if (kt < 16) {
            storeA(cur ^ 1, 0, pa0); storeA(cur ^ 1, 1, pa1);
            storeB(cur ^ 1, 0, pb0); storeB(cur ^ 1, 1, pb1);
            __syncthreads();
        }
    }
    // epilogue
    #pragma unroll
    for (int ii = 0; ii < 8; ii++) {
        int row = bm * 128 + tr * 8 + ii;
        #pragma unroll
        for (int jj = 0; jj < 8; jj++) {
            int col = bn * 128 + tc * 8 + jj;
            if (col < ND) {
                float r;
                if (MODE == 0) {
                    r = acc[ii][jj] + 32.f * bias[col];
                } else {
                    float z = acc[ii][jj] + bias[col];
                    r = fmaxf(z, 0.f) + log1pf(expf(-fabsf(z)));   // softplus
                }
                out[(size_t)row * ND + col] = r;
            }
        }
    }
}

// ---------------- stage 3a: loss partials (grid (4, B); chunk of 500 d each) ----------------
__global__ void k_loss_part(const float* __restrict__ target) {
    const int ch = blockIdx.x, b = blockIdx.y;
    const int tid = threadIdx.x;        // 256
    const int m = tid >> 4, n = tid & 15;
    const int dStart = ch * 500;
    __shared__ float sP[16 * 501];
    __shared__ float sT[500];

    #pragma unroll
    for (int i = 0; i < 32; i++) {      // 16*512 slots, 500 valid per row
        int idx = tid + i * 256;
        int row = idx >> 9, col = idx & 511;
        if (col < 500)
            sP[row * 501 + col] = g_P[(size_t)(b * NM + row) * ND + dStart + col];
    }
    for (int i = tid; i < 500; i += 256)
        sT[i] = target[(size_t)b * ND + dStart + i];
    __syncthreads();

    float inn = 0.f, td = 0.f;
    #pragma unroll 4
    for (int dd = 0; dd < 500; dd++) {
        float pm = sP[m * 501 + dd], pn = sP[n * 501 + dd];
        inn = fmaf(pm, pn, inn);
        if (m == n) { float df = pm - sT[dd]; td = fmaf(df, df, td); }
    }
    g_lossInn[(b * 4 + ch) * 256 + tid] = inn;
    if (m == n) g_lossTd[(b * 4 + ch) * 16 + m] = td;
}

// ---------------- stage 3b: loss combine per b ----------------
__global__ void k_loss_comb() {
    const int b = blockIdx.x;
    const int tid = threadIdx.x;        // 256
    const int m = tid >> 4, n = tid & 15;
    __shared__ float s_sq[16], s_td[16], s_w[8];

    float inn = 0.f;
    #pragma unroll
    for (int ch = 0; ch < 4; ch++) inn += g_lossInn[(b * 4 + ch) * 256 + tid];
    if (m == n) {
        float td = 0.f;
        #pragma unroll
        for (int ch = 0; ch < 4; ch++) td += g_lossTd[(b * 4 + ch) * 16 + m];
        s_sq[m] = inn; s_td[m] = td;
    }
    __syncthreads();
    float pd = 0.f;
    if (m != n) pd = sqrtf(fmaxf(s_sq[m] + s_sq[n] - 2.f * inn, 1e-6f));
    #pragma unroll
    for (int o = 16; o; o >>= 1) pd += __shfl_xor_sync(0xffffffffu, pd, o);
    if ((tid & 31) == 0) s_w[tid >> 5] = pd;
    __syncthreads();
    if (tid == 0) {
        float tot = 0.f;
        for (int w = 0; w < 8; w++) tot += s_w[w];
        float tc = 0.f;
        for (int mm = 0; mm < 16; mm++) tc += sqrtf(s_td[mm]);
        g_lossPart[b] = tc / 16.f - 0.5f * (tot / 240.f);   // LAM/2=0.5, M*(M-1)=240
    }
}

__global__ void k_loss_final(float* __restrict__ out, int off) {
    if (off >= 1 && threadIdx.x == 0 && blockIdx.x == 0) {
        float s = 0.f;
        for (int i = 0; i < NB; i++) s += g_lossPart[i];   // fixed order -> deterministic
        out[0] = s / (float)NB;
    }
}

// ---------------- stage 4: IPF, register-resident, cluster of 2 CTAs per b ----------------
// blockIdx.x = 2*b + rank; rank 0 owns g 0..15, rank 1 owns g 16..31.
// Thread owns 4 d-columns (tid + c*512) x 16 local g -> 64 y values in registers.
// Row sums are CTA-local; column sums exchanged via DSMEM once per iteration.
__global__ void __cluster_dims__(2, 1, 1) __launch_bounds__(512, 1)
k_ipf(const int* __restrict__ ts) {
    const int tid = threadIdx.x, lane = tid & 31, warp = tid >> 5;
    uint32_t rank;
    asm("mov.u32 %0, %%cluster_ctarank;" : "=r"(rank));
    const int b = blockIdx.x >> 1;
    float* yg = g_Y + (size_t)b * NG * ND + (size_t)rank * 16 * ND;
    const int* tsb = ts + (size_t)b * ND;

    __shared__ float s_colbuf[2][2048];
    __shared__ float s_red[16 * 16];    // [warp][g_local]
    __shared__ float s_R[16], s_rowfac[16];

    const uint32_t myColBase = smem_u32(&s_colbuf[0][0]);
    const uint32_t peerColBase = mapa_u32(myColBase, rank ^ 1u);

    int dIdx[4]; bool val[4];
    float C0[4], colsum[4], yv[16][4];
    #pragma unroll
    for (int c = 0; c < 4; c++) {
        dIdx[c] = tid + c * 512;
        val[c] = dIdx[c] < ND;
        C0[c] = val[c] ? fmaxf((float)__ldg(tsb + dIdx[c]), 0.f) : 0.f;
        colsum[c] = 0.f;
    }
    // load y slice; local column partials
    #pragma unroll
    for (int g = 0; g < 16; g++)
        #pragma unroll
        for (int c = 0; c < 4; c++) {
            yv[g][c] = val[c] ? fmaxf(yg[g * ND + dIdx[c]], 0.f) : 0.f;
            colsum[c] += yv[g][c];
        }

    // row anchors R (before smoothing, as in reference)
    {
        float rp[16];
        #pragma unroll
        for (int g = 0; g < 16; g++) {
            float v = yv[g][0] + yv[g][1] + yv[g][2] + yv[g][3];
            #pragma unroll
            for (int o = 16; o; o >>= 1) v += __shfl_xor_sync(0xffffffffu, v, o);
            rp[g] = v;
        }
        if (lane == 0) {
            #pragma unroll
            for (int g = 0; g < 16; g++) s_red[warp * 16 + g] = rp[g];
        }
        __syncthreads();
        if (tid < 16) {
            float s = 0.f;
            #pragma unroll
            for (int w = 0; w < 16; w++) s += s_red[w * 16 + tid];
            s_R[tid] = s;
        }
        __syncthreads();
    }

    // exchange initial column partials (buf 0)
    #pragma unroll
    for (int c = 0; c < 4; c++) s_colbuf[0][c * 512 + tid] = colsum[c];
    asm volatile("barrier.cluster.arrive.aligned;" ::: "memory");
    asm volatile("barrier.cluster.wait.aligned;" ::: "memory");
    #pragma unroll
    for (int c = 0; c < 4; c++) {
        float pv;
        asm volatile("ld.shared::cluster.f32 %0, [%1];"
                     : "=f"(pv) : "r"(peerColBase + (uint32_t)(c * 512 + tid) * 4u));
        colsum[c] += pv;
    }

    // col_zero smoothing (dead in practice — softplus > 0 — kept for exactness)
    #pragma unroll
    for (int c = 0; c < 4; c++) {
        if (val[c] && colsum[c] <= 0.f && C0[c] > 0.f) {
            #pragma unroll
            for (int g = 0; g < 16; g++) yv[g][c] += 1e-8f;
            colsum[c] += 32.f * 1e-8f;
        }
    }

    for (int it = 0; it < 60; it++) {
        float cf[4];
        #pragma unroll
        for (int c = 0; c < 4; c++)
            cf[c] = fminf(fmaxf(C0[c] / fmaxf(colsum[c], EPSC), 0.75f), 1.25f);
        // pass A: col scale + row partials
        float rp[16];
        #pragma unroll
        for (int g = 0; g < 16; g++) {
            float s = 0.f;
            #pragma unroll
            for (int c = 0; c < 4; c++) {
                float v = yv[g][c] * cf[c];
                yv[g][c] = v; s += v;
            }
            #pragma unroll
            for (int o = 16; o; o >>= 1) s += __shfl_xor_sync(0xffffffffu, s, o);
            rp[g] = s;
        }
        if (lane == 0) {
            #pragma unroll
            for (int g = 0; g < 16; g++) s_red[warp * 16 + g] = rp[g];
        }
        __syncthreads();
        if (tid < 16) {
            float s = 0.f;
            #pragma unroll
            for (int w = 0; w < 16; w++) s += s_red[w * 16 + tid];
            s_rowfac[tid] = fminf(fmaxf(s_R[tid] / fmaxf(s, EPSC), 0.75f), 1.25f);
        }
        __syncthreads();
        // pass B: row scale + next col partials
        #pragma unroll
        for (int c = 0; c < 4; c++) colsum[c] = 0.f;
        #pragma unroll
        for (int g = 0; g < 16; g++) {
            float rf = s_rowfac[g];
            #pragma unroll
            for (int c = 0; c < 4; c++) {
                float v = yv[g][c] * rf;
                yv[g][c] = v; colsum[c] += v;
            }
        }
        // exchange (double-buffered; one cluster barrier per iteration)
        int buf = (it + 1) & 1;
        #pragma unroll
        for (int c = 0; c < 4; c++) s_colbuf[buf][c * 512 + tid] = colsum[c];
        asm volatile("barrier.cluster.arrive.aligned;" ::: "memory");
        asm volatile("barrier.cluster.wait.aligned;" ::: "memory");
        #pragma unroll
        for (int c = 0; c < 4; c++) {
            float pv;
            asm volatile("ld.shared::cluster.f32 %0, [%1];"
                         : "=f"(pv)
                         : "r"(peerColBase + (uint32_t)(buf * 2048 + c * 512 + tid) * 4u));
            colsum[c] += pv;
        }
    }

    // cluster barrier before exit: peer must finish reading our smem
    asm volatile("barrier.cluster.arrive.aligned;" ::: "memory");
    asm volatile("barrier.cluster.wait.aligned;" ::: "memory");

    // final column normalization (no clamp) + write back
    #pragma unroll
    for (int c = 0; c < 4; c++) {
        if (val[c]) {
            float f = C0[c] / fmaxf(colsum[c], EPSC);
            #pragma unroll
            for (int g = 0; g < 16; g++) yg[g * ND + dIdx[c]] = yv[g][c] * f;
        }
    }
}

// ---------------- stage 5: exact integerization (smem-transposed tiles) ----------------
__global__ void k_round(const int* __restrict__ ts, float* __restrict__ out, int off) {
    const unsigned FULL = 0xffffffffu;
    const int b = blockIdx.y;
    const int d0 = blockIdx.x * 64;
    const int tid = threadIdx.x, lane = tid & 31, warp = tid >> 5;
    __shared__ float sy[32 * 65];
    __shared__ int   so[32 * 65];

    #pragma unroll
    for (int i = 0; i < 8; i++) {       // coalesced load of 32g x 64d tile
        int idx = tid + i * 256;
        int row = idx >> 6, col = idx & 63;
        int d = d0 + col;
        sy[row * 65 + col] = (d < ND) ? g_Y[(size_t)(b * NG + row) * ND + d] : 0.f;
    }
    __syncthreads();

    #pragma unroll
    for (int rep = 0; rep < 8; rep++) {
        int dcol = warp * 8 + rep;      // warp-uniform column
        int d = d0 + dcol;
        if (d < ND) {
            float v = fmaxf(sy[lane * 65 + dcol], 0.f);   // lane = g
            float xf = floorf(v);
            int yi = (int)xf;
            float fr = v - xf;
            int t = ts[(size_t)b * ND + d];

            int s = __reduce_add_sync(FULL, yi);
            int need = t - s;
            int pos = need > 0 ? need : 0;
            int q = pos >> 5;
            yi += q;
            int r = pos - (q << 5);
            // descending stable rank of fr (ties -> smaller index first)
            int cnt = 0;
            #pragma unroll
            for (int k = 1; k < 32; k++) {
                int j = (lane + k) & 31;
                float o = __shfl_sync(FULL, fr, j);
                cnt += (o > fr) || (o == fr && j < lane);
            }
            if (cnt < r) yi += 1;

            int s2 = __reduce_add_sync(FULL, yi);
            int need2 = t - s2;
            int neg = need2 < 0 ? -need2 : 0;
            neg = neg < s2 ? neg : s2;
            int q2 = neg >> 5;
            int yb = yi;
            yi -= q2; if (yi < 0) yi = 0;
            int removed = __reduce_add_sync(FULL, yb - yi);
            int r2 = neg - removed;
            float fm = (yi > 0) ? fr : __int_as_float(0x7f800000);  // +inf
            int cnt2 = 0;
            #pragma unroll
            for (int k = 1; k < 32; k++) {
                int j = (lane + k) & 31;
                float o = __shfl_sync(FULL, fm, j);
                cnt2 += (o < fm) || (o == fm && j < lane);
            }
            if (cnt2 < r2) yi -= 1;
            if (yi < 0) yi = 0;

            so[lane * 65 + dcol] = yi;
        }
    }
    __syncthreads();

    #pragma unroll
    for (int i = 0; i < 8; i++) {       // coalesced store
        int idx = tid + i * 256;
        int row = idx >> 6, col = idx & 63;
        int d = d0 + col;
        if (d < ND)
            out[(size_t)off + (size_t)(b * NG + row) * ND + d] = (float)so[row * 65 + col];
    }
}

// ---------------- launch (pure kernel launches; no runtime API calls) ----------------
extern "C" void kernel_launch(void* const* d_in, const int* in_sizes, int n_in,
                              void* d_out, int out_size) {
    const float* x      = (const float*)d_in[0];   // [2048,256]
    const float* target = (const float*)d_in[1];   // [64,2000]
    const int*   tsum   = (const int*)  d_in[2];   // [64,2000]
    const float* W      = (const float*)d_in[3];   // [272,2000]
    const float* bias   = (const float*)d_in[4];   // [2000]
    const float* nl     = (const float*)d_in[5];   // [32768,16]
    const float* ns     = (const float*)d_in[6];   // [2048,16]
    float* out = (float*)d_out;

    int off = out_size - NB * NG * ND;             // expected 1 (loss scalar first)
    if (off < 0) off = 0;

    // 1) group reductions
    k_reduce<<<128, 256>>>(x, nl);
    // 2) loss-path GEMM: g_P[1024,2000]
    k_gemm<0><<<dim3(16, 8), 256>>>(nullptr, nullptr, W, bias);
    // 3) sample GEMM with softplus: g_Y[2048,2000]
    k_gemm<1><<<dim3(16, 16), 256>>>(x, ns, W, bias);
    // 4) loss: partials -> per-b combine -> deterministic final sum
    k_loss_part<<<dim3(4, NB), 256>>>(target);
    k_loss_comb<<<NB, 256>>>();
    k_loss_final<<<1, 32>>>(out, off);
    // 5) IPF: register-resident, 2-CTA cluster per b
    k_ipf<<<2 * NB, 512>>>(tsum);
    // 6) exact integer rounding (tiled, coalesced)
    k_round<<<dim3(32, NB), 256>>>(tsum, out, off);
}

// round 8
// speedup vs baseline: 4.0920x; 1.3074x over previous
#include <cuda_runtime.h>
#include <math.h>
#include <stdint.h>

// Problem constants
#define NB   64      // num_groups (B)
#define NG   32      // group_size (G)
#define ND   2000    // output dim (D)
#define NM   16      // m_samples
#define NE   16      // noise dim
#define NDIN 256
#define KTOT 272     // DIN + E
#define EPSC 1e-12f

// ---------------- scratch (device globals; referenced directly by kernels) ----------------
__device__ __align__(16) float g_Xs[NB * NDIN];    // sum over g of x            [64,256]
__device__ __align__(16) float g_Ns[NB * NM * NE]; // sum over g of noise_loss   [1024,16]
__device__ __align__(16) float g_T [NB * ND];      // Xs·W1 + 32*bias            [64,2000]
__device__ __align__(16) float g_Y [NB * NG * ND]; // x_pred -> IPF y (in place) [2048,2000]
__device__ float g_lossInn[NB * 4 * 256];
__device__ float g_lossTd [NB * 4 * 16];
__device__ float g_lossPart[NB];

__device__ __forceinline__ uint32_t smem_u32(const void* p) {
    uint32_t a;
    asm("{ .reg .u64 t; cvta.to.shared.u64 t, %1; cvt.u32.u64 %0, t; }" : "=r"(a) : "l"(p));
    return a;
}
__device__ __forceinline__ uint32_t mapa_u32(uint32_t addr, uint32_t rank) {
    uint32_t r;
    asm("mapa.shared::cluster.u32 %0, %1, %2;" : "=r"(r) : "r"(addr), "r"(rank));
    return r;
}

// ---------------- stage 1: group reductions ----------------
__global__ void k_reduce(const float* __restrict__ x, const float* __restrict__ nl) {
    int i = blockIdx.x * 256 + threadIdx.x;
    if (i < NB * NDIN) {
        int b = i >> 8, k = i & 255;
        float s = 0.f;
        #pragma unroll 8
        for (int g = 0; g < NG; g++) s += x[(size_t)(b * NG + g) * NDIN + k];
        g_Xs[i] = s;
    } else {
        int j = i - NB * NDIN;             // j < 1024*16
        int row = j >> 4, e = j & 15;      // row = b*16 + m
        int b = row >> 4, m = row & 15;
        float s = 0.f;
        #pragma unroll 8
        for (int g = 0; g < NG; g++) s += nl[(size_t)((b * NG + g) * NM + m) * NE + e];
        g_Ns[j] = s;
    }
}

// ---------------- stage 2a: tiny GEMM  T[b,d] = Xs[b]·W1[:,d] + 32*bias[d] ----------------
// grid (8 dblk, 8 bblk), 256 threads; thread owns one d, 8 b's.
__global__ void k_gemmT(const float* __restrict__ W, const float* __restrict__ bias) {
    __shared__ float sXs[8 * 256];
    const int tid = threadIdx.x;
    const int dblk = blockIdx.x, bblk = blockIdx.y;
    #pragma unroll
    for (int i = 0; i < 8; i++) sXs[tid + i * 256] = g_Xs[bblk * 8 * 256 + tid + i * 256];
    __syncthreads();
    int d = dblk * 256 + tid;
    bool v = d < ND;
    float acc[8];
    #pragma unroll
    for (int i = 0; i < 8; i++) acc[i] = 0.f;
    #pragma unroll 4
    for (int k = 0; k < 256; k++) {
        float w = v ? W[(size_t)k * ND + d] : 0.f;
        #pragma unroll
        for (int i = 0; i < 8; i++) acc[i] = fmaf(sXs[i * 256 + k], w, acc[i]);
    }
    if (v) {
        float bi = 32.f * bias[d];
        #pragma unroll
        for (int i = 0; i < 8; i++) g_T[(size_t)(bblk * 8 + i) * ND + d] = acc[i] + bi;
    }
}

// ---------------- stage 2b: sample GEMM (fp32, packed f32x2 FMA, 2-stage pipeline) -------
// Y[2048,2000] = softplus( [x | noise_sample] · W + bias )
__global__ void __launch_bounds__(256, 2)
k_gemm1(const float* __restrict__ x, const float* __restrict__ ns,
        const float* __restrict__ W, const float* __restrict__ bias) {
    __shared__ __align__(16) float As[2][16 * 128];  // [buf][k][m]
    __shared__ __align__(16) float Bs[2][16 * 128];  // [buf][k][n]
    const int tid = threadIdx.x;                  // 256 threads
    const int bn = blockIdx.x, bm = blockIdx.y;
    const int tr = tid >> 4, tc = tid & 15;

    auto loadA = [&](int kt, int i) -> float4 {
        int idx = tid + i * 256;
        int kq = idx >> 7, row = idx & 127;
        int rowG = bm * 128 + row;
        if (kt < 16)
            return *(const float4*)(x + (size_t)rowG * NDIN + kt * 16 + kq * 4);
        return *(const float4*)(ns + (size_t)rowG * NE + kq * 4);
    };
    auto loadB = [&](int kt, int i) -> float4 {
        int idx = tid + i * 256;
        int kr = idx >> 5, cq = idx & 31;
        int d = bn * 128 + cq * 4;
        if (d < ND) return *(const float4*)(W + (size_t)(kt * 16 + kr) * ND + d);
        return make_float4(0.f, 0.f, 0.f, 0.f);
    };
    auto storeA = [&](int buf, int i, float4 v) {
        int idx = tid + i * 256;
        int kq = idx >> 7, row = idx & 127;
        As[buf][(kq * 4 + 0) * 128 + row] = v.x;
        As[buf][(kq * 4 + 1) * 128 + row] = v.y;
        As[buf][(kq * 4 + 2) * 128 + row] = v.z;
        As[buf][(kq * 4 + 3) * 128 + row] = v.w;
    };
    auto storeB = [&](int buf, int i, float4 v) {
        int idx = tid + i * 256;
        int kr = idx >> 5, cq = idx & 31;
        *(float4*)(&Bs[buf][kr * 128 + cq * 4]) = v;
    };

    unsigned long long acc2[8][4];       // packed f32x2 accumulators (jj pairs)
    #pragma unroll
    for (int i = 0; i < 8; i++)
        #pragma unroll
        for (int j = 0; j < 4; j++) acc2[i][j] = 0ull;

    float4 pa0 = loadA(0, 0), pa1 = loadA(0, 1);
    float4 pb0 = loadB(0, 0), pb1 = loadB(0, 1);
    storeA(0, 0, pa0); storeA(0, 1, pa1);
    storeB(0, 0, pb0); storeB(0, 1, pb1);
    __syncthreads();

    for (int kt = 0; kt < 17; kt++) {             // 272 = 17 * 16
        int cur = kt & 1;
        if (kt < 16) {
            pa0 = loadA(kt + 1, 0); pa1 = loadA(kt + 1, 1);
            pb0 = loadB(kt + 1, 0); pb1 = loadB(kt + 1, 1);
        }
        const float* Ab = As[cur];
        const float* Bb = Bs[cur];
        #pragma unroll
        for (int kk = 0; kk < 16; kk++) {
            float a[8];
            *(float4*)(a)     = *(const float4*)(Ab + kk * 128 + tr * 8);
            *(float4*)(a + 4) = *(const float4*)(Ab + kk * 128 + tr * 8 + 4);
            unsigned long long bp[4];
            {
                const float* bptr = Bb + kk * 128 + tc * 8;
                ulonglong2 t0 = *(const ulonglong2*)(bptr);
                ulonglong2 t1 = *(const ulonglong2*)(bptr + 4);
                bp[0] = t0.x; bp[1] = t0.y; bp[2] = t1.x; bp[3] = t1.y;
            }
            #pragma unroll
            for (int ii = 0; ii < 8; ii++) {
                unsigned long long ap;
                asm("mov.b64 %0, {%1, %1};" : "=l"(ap) : "f"(a[ii]));
                #pragma unroll
                for (int j = 0; j < 4; j++)
                    asm("fma.rn.f32x2 %0, %1, %2, %0;"
                        : "+l"(acc2[ii][j]) : "l"(ap), "l"(bp[j]));
            }
        }
        if (kt < 16) {
            storeA(cur ^ 1, 0, pa0); storeA(cur ^ 1, 1, pa1);
            storeB(cur ^ 1, 0, pb0); storeB(cur ^ 1, 1, pb1);
            __syncthreads();
        }
    }
    // epilogue: softplus(acc + bias)
    #pragma unroll
    for (int ii = 0; ii < 8; ii++) {
        int row = bm * 128 + tr * 8 + ii;
        #pragma unroll
        for (int j = 0; j < 4; j++) {
            float lo, hi;
            asm("mov.b64 {%0, %1}, %2;" : "=f"(lo), "=f"(hi) : "l"(acc2[ii][j]));
            int col = bn * 128 + tc * 8 + 2 * j;
            if (col < ND) {
                float z = lo + bias[col];
                g_Y[(size_t)row * ND + col] = fmaxf(z, 0.f) + log1pf(expf(-fabsf(z)));
            }
            if (col + 1 < ND) {
                float z = hi + bias[col + 1];
                g_Y[(size_t)row * ND + col + 1] = fmaxf(z, 0.f) + log1pf(expf(-fabsf(z)));
            }
        }
    }
}

// ---------------- stage 3a: loss partials, P built on the fly from T + Ns·W2 -------------
__global__ void k_loss_part(const float* __restrict__ target, const float* __restrict__ W) {
    const int ch = blockIdx.x, b = blockIdx.y;
    const int tid = threadIdx.x;        // 256
    const int m = tid >> 4, n = tid & 15;
    const int dStart = ch * 500;
    __shared__ float sP[16 * 513];
    __shared__ float sT[500];
    __shared__ float sNs[256];          // [m][e]

    sNs[tid] = g_Ns[b * 256 + tid];
    __syncthreads();

    for (int dd = tid; dd < 500; dd += 256) {
        int d = dStart + dd;
        float t0 = g_T[(size_t)b * ND + d];
        float w[16];
        #pragma unroll
        for (int e = 0; e < 16; e++) w[e] = W[(size_t)(256 + e) * ND + d];
        #pragma unroll
        for (int mm = 0; mm < 16; mm++) {
            float p = t0;
            #pragma unroll
            for (int e = 0; e < 16; e++) p = fmaf(sNs[mm * 16 + e], w[e], p);
            sP[mm * 513 + dd] = p;
        }
        sT[dd] = target[(size_t)b * ND + d];
    }
    __syncthreads();

    float inn = 0.f, td = 0.f;
    #pragma unroll 4
    for (int dd = 0; dd < 500; dd++) {
        float pm = sP[m * 513 + dd], pn = sP[n * 513 + dd];
        inn = fmaf(pm, pn, inn);
        if (m == n) { float df = pm - sT[dd]; td = fmaf(df, df, td); }
    }
    g_lossInn[(b * 4 + ch) * 256 + tid] = inn;
    if (m == n) g_lossTd[(b * 4 + ch) * 16 + m] = td;
}

// ---------------- stage 3b: loss combine per b ----------------
__global__ void k_loss_comb() {
    const int b = blockIdx.x;
    const int tid = threadIdx.x;        // 256
    const int m = tid >> 4, n = tid & 15;
    __shared__ float s_sq[16], s_td[16], s_w[8];

    float inn = 0.f;
    #pragma unroll
    for (int ch = 0; ch < 4; ch++) inn += g_lossInn[(b * 4 + ch) * 256 + tid];
    if (m == n) {
        float td = 0.f;
        #pragma unroll
        for (int ch = 0; ch < 4; ch++) td += g_lossTd[(b * 4 + ch) * 16 + m];
        s_sq[m] = inn; s_td[m] = td;
    }
    __syncthreads();
    float pd = 0.f;
    if (m != n) pd = sqrtf(fmaxf(s_sq[m] + s_sq[n] - 2.f * inn, 1e-6f));
    #pragma unroll
    for (int o = 16; o; o >>= 1) pd += __shfl_xor_sync(0xffffffffu, pd, o);
    if ((tid & 31) == 0) s_w[tid >> 5] = pd;
    __syncthreads();
    if (tid == 0) {
        float tot = 0.f;
        for (int w = 0; w < 8; w++) tot += s_w[w];
        float tc = 0.f;
        for (int mm = 0; mm < 16; mm++) tc += sqrtf(s_td[mm]);
        g_lossPart[b] = tc / 16.f - 0.5f * (tot / 240.f);   // LAM/2=0.5, M*(M-1)=240
    }
}

__global__ void k_loss_final(float* __restrict__ out, int off) {
    if (off >= 1 && threadIdx.x == 0 && blockIdx.x == 0) {
        float s = 0.f;
        for (int i = 0; i < NB; i++) s += g_lossPart[i];   // fixed order -> deterministic
        out[0] = s / (float)NB;
    }
}

// ---- multi-value butterfly: reduce 16 row sums across a warp in 16 shfls ----
// On return: even lanes hold the full-warp sum for g = gheld.
__device__ __forceinline__ void warp_reduce16(float v[16], int lane,
                                              float& out, int& gheld) {
    const unsigned FULL = 0xffffffffu;
    #pragma unroll
    for (int i = 0; i < 8; i++) {
        float send = (lane & 16) ? v[i] : v[i + 8];
        float recv = __shfl_xor_sync(FULL, send, 16);
        v[i] = ((lane & 16) ? v[i + 8] : v[i]) + recv;
    }
    #pragma unroll
    for (int i = 0; i < 4; i++) {
        float send = (lane & 8) ? v[i] : v[i + 4];
        float recv = __shfl_xor_sync(FULL, send, 8);
        v[i] = ((lane & 8) ? v[i + 4] : v[i]) + recv;
    }
    #pragma unroll
    for (int i = 0; i < 2; i++) {
        float send = (lane & 4) ? v[i] : v[i + 2];
        float recv = __shfl_xor_sync(FULL, send, 4);
        v[i] = ((lane & 4) ? v[i + 2] : v[i]) + recv;
    }
    {
        float send = (lane & 2) ? v[0] : v[1];
        float recv = __shfl_xor_sync(FULL, send, 2);
        v[0] = ((lane & 2) ? v[1] : v[0]) + recv;
    }
    v[0] += __shfl_xor_sync(FULL, v[0], 1);
    gheld = ((lane >> 1) & 1) | (((lane >> 2) & 1) << 1)
          | (((lane >> 3) & 1) << 2) | (((lane >> 4) & 1) << 3);
    out = v[0];
}

// ---------------- stage 4: IPF, register-resident, cluster of 2 CTAs per b ----------------
__global__ void __cluster_dims__(2, 1, 1) __launch_bounds__(512, 1)
k_ipf(const int* __restrict__ ts) {
    const int tid = threadIdx.x, lane = tid & 31, warp = tid >> 5;
    uint32_t rank;
    asm("mov.u32 %0, %%cluster_ctarank;" : "=r"(rank));
    const int b = blockIdx.x >> 1;
    float* yg = g_Y + (size_t)b * NG * ND + (size_t)rank * 16 * ND;
    const int* tsb = ts + (size_t)b * ND;

    __shared__ float s_colbuf[2][2048];
    __shared__ float s_red[16 * 16];    // [warp][g_local]
    __shared__ float s_R[16], s_rowfac[16];

    const uint32_t myColBase = smem_u32(&s_colbuf[0][0]);
    const uint32_t peerColBase = mapa_u32(myColBase, rank ^ 1u);

    int dIdx[4]; bool val[4];
    float C0[4], colsum[4], yv[16][4];
    #pragma unroll
    for (int c = 0; c < 4; c++) {
        dIdx[c] = tid + c * 512;
        val[c] = dIdx[c] < ND;
        C0[c] = val[c] ? fmaxf((float)__ldg(tsb + dIdx[c]), 0.f) : 0.f;
        colsum[c] = 0.f;
    }
    #pragma unroll
    for (int g = 0; g < 16; g++)
        #pragma unroll
        for (int c = 0; c < 4; c++) {
            yv[g][c] = val[c] ? fmaxf(yg[g * ND + dIdx[c]], 0.f) : 0.f;
            colsum[c] += yv[g][c];
        }

    // row anchors R (pre-smoothing, as in reference)
    {
        float rs[16];
        #pragma unroll
        for (int g = 0; g < 16; g++)
            rs[g] = yv[g][0] + yv[g][1] + yv[g][2] + yv[g][3];
        float out; int gh;
        warp_reduce16(rs, lane, out, gh);
        if (!(lane & 1)) s_red[warp * 16 + gh] = out;
        __syncthreads();
        if (tid < 16) {
            float s = 0.f;
            #pragma unroll
            for (int w = 0; w < 16; w++) s += s_red[w * 16 + tid];
            s_R[tid] = s;
        }
        __syncthreads();
    }

    // exchange initial column partials (buf 0)
    #pragma unroll
    for (int c = 0; c < 4; c++) s_colbuf[0][c * 512 + tid] = colsum[c];
    asm volatile("barrier.cluster.arrive.aligned;" ::: "memory");
    asm volatile("barrier.cluster.wait.aligned;" ::: "memory");
    #pragma unroll
    for (int c = 0; c < 4; c++) {
        float pv;
        asm volatile("ld.shared::cluster.f32 %0, [%1];"
                     : "=f"(pv) : "r"(peerColBase + (uint32_t)(c * 512 + tid) * 4u));
        colsum[c] += pv;
    }

    // col_zero smoothing (dead in practice — softplus > 0 — kept for exactness)
    #pragma unroll
    for (int c = 0; c < 4; c++) {
        if (val[c] && colsum[c] <= 0.f && C0[c] > 0.f) {
            #pragma unroll
            for (int g = 0; g < 16; g++) yv[g][c] += 1e-8f;
            colsum[c] += 32.f * 1e-8f;
        }
    }

    for (int it = 0; it < 60; it++) {
        float cf[4];
        #pragma unroll
        for (int c = 0; c < 4; c++)
            cf[c] = fminf(fmaxf(C0[c] / fmaxf(colsum[c], EPSC), 0.75f), 1.25f);
        // pass A: col scale + row sums (butterfly)
        float rs[16];
        #pragma unroll
        for (int g = 0; g < 16; g++) {
            float s = 0.f;
            #pragma unroll
            for (int c = 0; c < 4; c++) {
                float v = yv[g][c] * cf[c];
                yv[g][c] = v; s += v;
            }
            rs[g] = s;
        }
        {
            float out; int gh;
            warp_reduce16(rs, lane, out, gh);
            if (!(lane & 1)) s_red[warp * 16 + gh] = out;
        }
        __syncthreads();
        if (tid < 16) {
            float s = 0.f;
            #pragma unroll
            for (int w = 0; w < 16; w++) s += s_red[w * 16 + tid];
            s_rowfac[tid] = fminf(fmaxf(s_R[tid] / fmaxf(s, EPSC), 0.75f), 1.25f);
        }
        __syncthreads();
        // pass B: row scale + next col partials
        #pragma unroll
        for (int c = 0; c < 4; c++) colsum[c] = 0.f;
        #pragma unroll
        for (int g = 0; g < 16; g++) {
            float rf = s_rowfac[g];
            #pragma unroll
            for (int c = 0; c < 4; c++) {
                float v = yv[g][c] * rf;
                yv[g][c] = v; colsum[c] += v;
            }
        }
        // exchange (double-buffered; one cluster barrier per iteration)
        int buf = (it + 1) & 1;
        #pragma unroll
        for (int c = 0; c < 4; c++) s_colbuf[buf][c * 512 + tid] = colsum[c];
        asm volatile("barrier.cluster.arrive.aligned;" ::: "memory");
        asm volatile("barrier.cluster.wait.aligned;" ::: "memory");
        #pragma unroll
        for (int c = 0; c < 4; c++) {
            float pv;
            asm volatile("ld.shared::cluster.f32 %0, [%1];"
                         : "=f"(pv)
                         : "r"(peerColBase + (uint32_t)(buf * 2048 + c * 512 + tid) * 4u));
            colsum[c] += pv;
        }
    }

    // cluster barrier before exit: peer must finish reading our smem
    asm volatile("barrier.cluster.arrive.aligned;" ::: "memory");
    asm volatile("barrier.cluster.wait.aligned;" ::: "memory");

    // final column normalization (no clamp) + write back
    #pragma unroll
    for (int c = 0; c < 4; c++) {
        if (val[c]) {
            float f = C0[c] / fmaxf(colsum[c], EPSC);
            #pragma unroll
            for (int g = 0; g < 16; g++) yg[g * ND + dIdx[c]] = yv[g][c] * f;
        }
    }
}

// ---------------- stage 5: exact integerization (smem-transposed tiles) ----------------
__global__ void k_round(const int* __restrict__ ts, float* __restrict__ out, int off) {
    const unsigned FULL = 0xffffffffu;
    const int b = blockIdx.y;
    const int d0 = blockIdx.x * 64;
    const int tid = threadIdx.x, lane = tid & 31, warp = tid >> 5;
    __shared__ float sy[32 * 65];
    __shared__ int   so[32 * 65];

    #pragma unroll
    for (int i = 0; i < 8; i++) {       // coalesced load of 32g x 64d tile
        int idx = tid + i * 256;
        int row = idx >> 6, col = idx & 63;
        int d = d0 + col;
        sy[row * 65 + col] = (d < ND) ? g_Y[(size_t)(b * NG + row) * ND + d] : 0.f;
    }
    __syncthreads();

    #pragma unroll
    for (int rep = 0; rep < 8; rep++) {
        int dcol = warp * 8 + rep;      // warp-uniform column
        int d = d0 + dcol;
        if (d < ND) {
            float v = fmaxf(sy[lane * 65 + dcol], 0.f);   // lane = g
            float xf = floorf(v);
            int yi = (int)xf;
            float fr = v - xf;
            int t = ts[(size_t)b * ND + d];

            int s = __reduce_add_sync(FULL, yi);
            int need = t - s;
            int pos = need > 0 ? need : 0;
            int q = pos >> 5;
            yi += q;
            int r = pos - (q << 5);
            if (r > 0) {                // warp-uniform guard
                // descending stable rank of fr (ties -> smaller index first)
                int cnt = 0;
                #pragma unroll
                for (int k = 1; k < 32; k++) {
                    int j = (lane + k) & 31;
                    float o = __shfl_sync(FULL, fr, j);
                    cnt += (o > fr) || (o == fr && j < lane);
                }
                if (cnt < r) yi += 1;
            }

            int s2 = __reduce_add_sync(FULL, yi);
            int need2 = t - s2;
            int neg = need2 < 0 ? -need2 : 0;
            neg = neg < s2 ? neg : s2;
            if (neg > 0) {              // warp-uniform guard
                int q2 = neg >> 5;
                int yb = yi;
                yi -= q2; if (yi < 0) yi = 0;
                int removed = __reduce_add_sync(FULL, yb - yi);
                int r2 = neg - removed;
                if (r2 > 0) {
                    float fm = (yi > 0) ? fr : __int_as_float(0x7f800000);  // +inf
                    int cnt2 = 0;
                    #pragma unroll
                    for (int k = 1; k < 32; k++) {
                        int j = (lane + k) & 31;
                        float o = __shfl_sync(FULL, fm, j);
                        cnt2 += (o < fm) || (o == fm && j < lane);
                    }
                    if (cnt2 < r2) yi -= 1;
                    if (yi < 0) yi = 0;
                }
            }
            so[lane * 65 + dcol] = yi;
        }
    }
    __syncthreads();

    #pragma unroll
    for (int i = 0; i < 8; i++) {       // coalesced store
        int idx = tid + i * 256;
        int row = idx >> 6, col = idx & 63;
        int d = d0 + col;
        if (d < ND)
            out[(size_t)off + (size_t)(b * NG + row) * ND + d] = (float)so[row * 65 + col];
    }
}

// ---------------- launch (pure kernel launches; no runtime API calls) ----------------
extern "C" void kernel_launch(void* const* d_in, const int* in_sizes, int n_in,
                              void* d_out, int out_size) {
    const float* x      = (const float*)d_in[0];   // [2048,256]
    const float* target = (const float*)d_in[1];   // [64,2000]
    const int*   tsum   = (const int*)  d_in[2];   // [64,2000]
    const float* W      = (const float*)d_in[3];   // [272,2000]
    const float* bias   = (const float*)d_in[4];   // [2000]
    const float* nl     = (const float*)d_in[5];   // [32768,16]
    const float* ns     = (const float*)d_in[6];   // [2048,16]
    float* out = (float*)d_out;

    int off = out_size - NB * NG * ND;             // expected 1 (loss scalar first)
    if (off < 0) off = 0;

    // 1) group reductions
    k_reduce<<<128, 256>>>(x, nl);
    // 2a) sample GEMM with softplus (f32x2 packed math): g_Y[2048,2000]
    k_gemm1<<<dim3(16, 16), 256>>>(x, ns, W, bias);
    // 2b) tiny loss-path GEMM: g_T[64,2000]
    k_gemmT<<<dim3(8, 8), 256>>>(W, bias);
    // 3) loss: partials (P rebuilt on the fly) -> per-b combine -> final sum
    k_loss_part<<<dim3(4, NB), 256>>>(target, W);
    k_loss_comb<<<NB, 256>>>();
    k_loss_final<<<1, 32>>>(out, off);
    // 4) IPF: register-resident, 2-CTA cluster per b
    k_ipf<<<2 * NB, 512>>>(tsum);
    // 5) exact integer rounding (tiled, coalesced)
    k_round<<<dim3(32, NB), 256>>>(tsum, out, off);
}

// round 10
// speedup vs baseline: 4.3190x; 1.0555x over previous
#include <cuda_runtime.h>
#include <math.h>
#include <stdint.h>

// Problem constants
#define NB   64      // num_groups (B)
#define NG   32      // group_size (G)
#define ND   2000    // output dim (D)
#define NM   16      // m_samples
#define NE   16      // noise dim
#define NDIN 256
#define KTOT 272     // DIN + E
#define EPSC 1e-12f
#define NCH  8       // loss d-chunks
#define CHD  250     // d per chunk
#define SPD  253     // sP stride (odd -> conflict-free)

// ---------------- scratch (device globals; referenced directly by kernels) ----------------
__device__ __align__(16) float g_Xs[NB * NDIN];    // sum over g of x            [64,256]
__device__ __align__(16) float g_Ns[NB * NM * NE]; // sum over g of noise_loss   [1024,16]
__device__ __align__(16) float g_Tp[4][NB * ND];   // k-split partials of Xs·W1  4x[64,2000]
__device__ __align__(16) float g_Y [NB * NG * ND]; // x_pred -> IPF y (in place) [2048,2000]
__device__ float g_lossInn[NB * NCH * 256];
__device__ float g_lossTd [NB * NCH * 16];
__device__ float g_lossPart[NB];

__device__ __forceinline__ uint32_t smem_u32(const void* p) {
    uint32_t a;
    asm("{ .reg .u64 t; cvta.to.shared.u64 t, %1; cvt.u32.u64 %0, t; }" : "=r"(a) : "l"(p));
    return a;
}
__device__ __forceinline__ uint32_t mapa_u32(uint32_t addr, uint32_t rank) {
    uint32_t r;
    asm("mapa.shared::cluster.u32 %0, %1, %2;" : "=r"(r) : "r"(addr), "r"(rank));
    return r;
}

// ---------------- stage 1: group reductions ----------------
__global__ void k_reduce(const float* __restrict__ x, const float* __restrict__ nl) {
    int i = blockIdx.x * 256 + threadIdx.x;
    if (i < NB * NDIN) {
        int b = i >> 8, k = i & 255;
        float s = 0.f;
        #pragma unroll 8
        for (int g = 0; g < NG; g++) s += x[(size_t)(b * NG + g) * NDIN + k];
        g_Xs[i] = s;
    } else {
        int j = i - NB * NDIN;             // j < 1024*16
        int row = j >> 4, e = j & 15;      // row = b*16 + m
        int b = row >> 4, m = row & 15;
        float s = 0.f;
        #pragma unroll 8
        for (int g = 0; g < NG; g++) s += nl[(size_t)((b * NG + g) * NM + m) * NE + e];
        g_Ns[j] = s;
    }
}

// ---------------- stage 2a: tiny GEMM, k-split x4: Tp[kb][b,d] = Xs[b,k0:k0+64]·W1 --------
// grid (8 dblk, 8 bblk, 4 kblk), 256 threads; thread owns one d, 8 b's, 64 k.
__global__ void k_gemmT(const float* __restrict__ W, const float* __restrict__ bias) {
    __shared__ float sXs[8 * 64];          // [b_local][k_local]
    const int tid = threadIdx.x;
    const int dblk = blockIdx.x, bblk = blockIdx.y, kblk = blockIdx.z;
    const int k0 = kblk * 64;
    if (tid < 512 - 256) { /* nothing */ }
    #pragma unroll
    for (int i = tid; i < 8 * 64; i += 256) {
        int bl = i >> 6, kk = i & 63;
        sXs[i] = g_Xs[(bblk * 8 + bl) * NDIN + k0 + kk];
    }
    __syncthreads();
    int d = dblk * 256 + tid;
    bool v = d < ND;
    float acc[8];
    #pragma unroll
    for (int i = 0; i < 8; i++) acc[i] = 0.f;
    #pragma unroll 8
    for (int k = 0; k < 64; k++) {
        float w = v ? W[(size_t)(k0 + k) * ND + d] : 0.f;
        #pragma unroll
        for (int i = 0; i < 8; i++) acc[i] = fmaf(sXs[i * 64 + k], w, acc[i]);
    }
    if (v) {
        float add = (kblk == 0) ? 32.f * bias[d] : 0.f;
        #pragma unroll
        for (int i = 0; i < 8; i++)
            g_Tp[kblk][(size_t)(bblk * 8 + i) * ND + d] = acc[i] + add;
    }
}

// ---------------- stage 2b: sample GEMM (fp32, packed f32x2 FMA, 2-stage pipeline) -------
__global__ void __launch_bounds__(256, 2)
k_gemm1(const float* __restrict__ x, const float* __restrict__ ns,
        const float* __restrict__ W, const float* __restrict__ bias) {
    __shared__ __align__(16) float As[2][16 * 128];  // [buf][k][m]
    __shared__ __align__(16) float Bs[2][16 * 128];  // [buf][k][n]
    const int tid = threadIdx.x;                  // 256 threads
    const int bn = blockIdx.x, bm = blockIdx.y;
    const int tr = tid >> 4, tc = tid & 15;

    auto loadA = [&](int kt, int i) -> float4 {
        int idx = tid + i * 256;
        int kq = idx >> 7, row = idx & 127;
        int rowG = bm * 128 + row;
        if (kt < 16)
            return *(const float4*)(x + (size_t)rowG * NDIN + kt * 16 + kq * 4);
        return *(const float4*)(ns + (size_t)rowG * NE + kq * 4);
    };
    auto loadB = [&](int kt, int i) -> float4 {
        int idx = tid + i * 256;
        int kr = idx >> 5, cq = idx & 31;
        int d = bn * 128 + cq * 4;
        if (d < ND) return *(const float4*)(W + (size_t)(kt * 16 + kr) * ND + d);
        return make_float4(0.f, 0.f, 0.f, 0.f);
    };
    auto storeA = [&](int buf, int i, float4 v) {
        int idx = tid + i * 256;
        int kq = idx >> 7, row = idx & 127;
        As[buf][(kq * 4 + 0) * 128 + row] = v.x;
        As[buf][(kq * 4 + 1) * 128 + row] = v.y;
        As[buf][(kq * 4 + 2) * 128 + row] = v.z;
        As[buf][(kq * 4 + 3) * 128 + row] = v.w;
    };
    auto storeB = [&](int buf, int i, float4 v) {
        int idx = tid + i * 256;
        int kr = idx >> 5, cq = idx & 31;
        *(float4*)(&Bs[buf][kr * 128 + cq * 4]) = v;
    };

    unsigned long long acc2[8][4];       // packed f32x2 accumulators (jj pairs)
    #pragma unroll
    for (int i = 0; i < 8; i++)
        #pragma unroll
        for (int j = 0; j < 4; j++) acc2[i][j] = 0ull;

    float4 pa0 = loadA(0, 0), pa1 = loadA(0, 1);
    float4 pb0 = loadB(0, 0), pb1 = loadB(0, 1);
    storeA(0, 0, pa0); storeA(0, 1, pa1);
    storeB(0, 0, pb0); storeB(0, 1, pb1);
    __syncthreads();

    for (int kt = 0; kt < 17; kt++) {             // 272 = 17 * 16
        int cur = kt & 1;
        if (kt < 16) {
            pa0 = loadA(kt + 1, 0); pa1 = loadA(kt + 1, 1);
            pb0 = loadB(kt + 1, 0); pb1 = loadB(kt + 1, 1);
        }
        const float* Ab = As[cur];
        const float* Bb = Bs[cur];
        #pragma unroll
        for (int kk = 0; kk < 16; kk++) {
            float a[8];
            *(float4*)(a)     = *(const float4*)(Ab + kk * 128 + tr * 8);
            *(float4*)(a + 4) = *(const float4*)(Ab + kk * 128 + tr * 8 + 4);
            unsigned long long bp[4];
            {
                const float* bptr = Bb + kk * 128 + tc * 8;
                ulonglong2 t0 = *(const ulonglong2*)(bptr);
                ulonglong2 t1 = *(const ulonglong2*)(bptr + 4);
                bp[0] = t0.x; bp[1] = t0.y; bp[2] = t1.x; bp[3] = t1.y;
            }
            #pragma unroll
            for (int ii = 0; ii < 8; ii++) {
                unsigned long long ap;
                asm("mov.b64 %0, {%1, %1};" : "=l"(ap) : "f"(a[ii]));
                #pragma unroll
                for (int j = 0; j < 4; j++)
                    asm("fma.rn.f32x2 %0, %1, %2, %0;"
                        : "+l"(acc2[ii][j]) : "l"(ap), "l"(bp[j]));
            }
        }
        if (kt < 16) {
            storeA(cur ^ 1, 0, pa0); storeA(cur ^ 1, 1, pa1);
            storeB(cur ^ 1, 0, pb0); storeB(cur ^ 1, 1, pb1);
            __syncthreads();
        }
    }
    // epilogue: softplus(acc + bias)
    #pragma unroll
    for (int ii = 0; ii < 8; ii++) {
        int row = bm * 128 + tr * 8 + ii;
        #pragma unroll
        for (int j = 0; j < 4; j++) {
            float lo, hi;
            asm("mov.b64 {%0, %1}, %2;" : "=f"(lo), "=f"(hi) : "l"(acc2[ii][j]));
            int col = bn * 128 + tc * 8 + 2 * j;
            if (col < ND) {
                float z = lo + bias[col];
                g_Y[(size_t)row * ND + col] = fmaxf(z, 0.f) + log1pf(expf(-fabsf(z)));
            }
            if (col + 1 < ND) {
                float z = hi + bias[col + 1];
                g_Y[(size_t)row * ND + col + 1] = fmaxf(z, 0.f) + log1pf(expf(-fabsf(z)));
            }
        }
    }
}

// ---------------- stage 3a: loss partials, P built on the fly (low-reg restructure) ------
__global__ void __launch_bounds__(256, 4)
k_loss_part(const float* __restrict__ target, const float* __restrict__ W) {
    const int ch = blockIdx.x, b = blockIdx.y;
    const int tid = threadIdx.x;        // 256
    const int m = tid >> 4, n = tid & 15;
    const int dStart = ch * CHD;
    __shared__ float sP[16 * SPD];
    __shared__ float sT[CHD];
    __shared__ float sNs[256];          // [m][e]

    sNs[tid] = g_Ns[b * 256 + tid];
    __syncthreads();

    if (tid < CHD) {
        int dd = tid, d = dStart + dd;
        float p[16];
        float t0 = g_Tp[0][(size_t)b * ND + d] + g_Tp[1][(size_t)b * ND + d]
                 + g_Tp[2][(size_t)b * ND + d] + g_Tp[3][(size_t)b * ND + d];
        #pragma unroll
        for (int mm = 0; mm < 16; mm++) p[mm] = t0;
        #pragma unroll
        for (int e = 0; e < 16; e++) {
            float w = W[(size_t)(256 + e) * ND + d];
            #pragma unroll
            for (int mm = 0; mm < 16; mm++)
                p[mm] = fmaf(sNs[mm * 16 + e], w, p[mm]);   // sNs read is warp-uniform
        }
        #pragma unroll
        for (int mm = 0; mm < 16; mm++) sP[mm * SPD + dd] = p[mm];
        sT[dd] = target[(size_t)b * ND + d];
    }
    __syncthreads();

    float inn = 0.f, td = 0.f;
    #pragma unroll 2
    for (int dd = 0; dd < CHD; dd++) {
        float pm = sP[m * SPD + dd], pn = sP[n * SPD + dd];
        inn = fmaf(pm, pn, inn);
        if (m == n) { float df = pm - sT[dd]; td = fmaf(df, df, td); }
    }
    g_lossInn[(b * NCH + ch) * 256 + tid] = inn;
    if (m == n) g_lossTd[(b * NCH + ch) * 16 + m] = td;
}

// ---------------- stage 3b: loss combine per b ----------------
__global__ void k_loss_comb() {
    const int b = blockIdx.x;
    const int tid = threadIdx.x;        // 256
    const int m = tid >> 4, n = tid & 15;
    __shared__ float s_sq[16], s_td[16], s_w[8];

    float inn = 0.f;
    #pragma unroll
    for (int ch = 0; ch < NCH; ch++) inn += g_lossInn[(b * NCH + ch) * 256 + tid];
    if (m == n) {
        float td = 0.f;
        #pragma unroll
        for (int ch = 0; ch < NCH; ch++) td += g_lossTd[(b * NCH + ch) * 16 + m];
        s_sq[m] = inn; s_td[m] = td;
    }
    __syncthreads();
    float pd = 0.f;
    if (m != n) pd = sqrtf(fmaxf(s_sq[m] + s_sq[n] - 2.f * inn, 1e-6f));
    #pragma unroll
    for (int o = 16; o; o >>= 1) pd += __shfl_xor_sync(0xffffffffu, pd, o);
    if ((tid & 31) == 0) s_w[tid >> 5] = pd;
    __syncthreads();
    if (tid == 0) {
        float tot = 0.f;
        for (int w = 0; w < 8; w++) tot += s_w[w];
        float tc = 0.f;
        for (int mm = 0; mm < 16; mm++) tc += sqrtf(s_td[mm]);
        g_lossPart[b] = tc / 16.f - 0.5f * (tot / 240.f);   // LAM/2=0.5, M*(M-1)=240
    }
}

__global__ void k_loss_final(float* __restrict__ out, int off) {
    if (off >= 1 && threadIdx.x == 0 && blockIdx.x == 0) {
        float s = 0.f;
        for (int i = 0; i < NB; i++) s += g_lossPart[i];   // fixed order -> deterministic
        out[0] = s / (float)NB;
    }
}

// ---- multi-value butterfly: reduce 16 row sums across a warp in 16 shfls ----
__device__ __forceinline__ void warp_reduce16(float v[16], int lane,
                                              float& out, int& gheld) {
    const unsigned FULL = 0xffffffffu;
    #pragma unroll
    for (int i = 0; i < 8; i++) {
        float send = (lane & 16) ? v[i] : v[i + 8];
        float recv = __shfl_xor_sync(FULL, send, 16);
        v[i] = ((lane & 16) ? v[i + 8] : v[i]) + recv;
    }
    #pragma unroll
    for (int i = 0; i < 4; i++) {
        float send = (lane & 8) ? v[i] : v[i + 4];
        float recv = __shfl_xor_sync(FULL, send, 8);
        v[i] = ((lane & 8) ? v[i + 4] : v[i]) + recv;
    }
    #pragma unroll
    for (int i = 0; i < 2; i++) {
        float send = (lane & 4) ? v[i] : v[i + 2];
        float recv = __shfl_xor_sync(FULL, send, 4);
        v[i] = ((lane & 4) ? v[i + 2] : v[i]) + recv;
    }
    {
        float send = (lane & 2) ? v[0] : v[1];
        float recv = __shfl_xor_sync(FULL, send, 2);
        v[0] = ((lane & 2) ? v[1] : v[0]) + recv;
    }
    v[0] += __shfl_xor_sync(FULL, v[0], 1);
    gheld = ((lane >> 1) & 1) | (((lane >> 2) & 1) << 1)
          | (((lane >> 3) & 1) << 2) | (((lane >> 4) & 1) << 3);
    out = v[0];
}

// ---------------- stage 4: IPF, register-resident, cluster of 2 CTAs per b ----------------
__global__ void __cluster_dims__(2, 1, 1) __launch_bounds__(512, 1)
k_ipf(const int* __restrict__ ts) {
    const int tid = threadIdx.x, lane = tid & 31, warp = tid >> 5;
    uint32_t rank;
    asm("mov.u32 %0, %%cluster_ctarank;" : "=r"(rank));
    const int b = blockIdx.x >> 1;
    float* yg = g_Y + (size_t)b * NG * ND + (size_t)rank * 16 * ND;
    const int* tsb = ts + (size_t)b * ND;

    __shared__ float s_colbuf[2][2048];
    __shared__ float s_red[16 * 16];    // [warp][g_local]
    __shared__ float s_R[16], s_rowfac[16];

    const uint32_t myColBase = smem_u32(&s_colbuf[0][0]);
    const uint32_t peerColBase = mapa_u32(myColBase, rank ^ 1u);

    int dIdx[4]; bool val[4];
    float C0[4], colsum[4], yv[16][4];
    #pragma unroll
    for (int c = 0; c < 4; c++) {
        dIdx[c] = tid + c * 512;
        val[c] = dIdx[c] < ND;
        C0[c] = val[c] ? fmaxf((float)__ldg(tsb + dIdx[c]), 0.f) : 0.f;
        colsum[c] = 0.f;
    }
    #pragma unroll
    for (int g = 0; g < 16; g++)
        #pragma unroll
        for (int c = 0; c < 4; c++) {
            yv[g][c] = val[c] ? fmaxf(yg[g * ND + dIdx[c]], 0.f) : 0.f;
            colsum[c] += yv[g][c];
        }

    // row anchors R (pre-smoothing, as in reference)
    {
        float rs[16];
        #pragma unroll
        for (int g = 0; g < 16; g++)
            rs[g] = yv[g][0] + yv[g][1] + yv[g][2] + yv[g][3];
        float out; int gh;
        warp_reduce16(rs, lane, out, gh);
        if (!(lane & 1)) s_red[warp * 16 + gh] = out;
        __syncthreads();
        if (tid < 16) {
            float s = 0.f;
            #pragma unroll
            for (int w = 0; w < 16; w++) s += s_red[w * 16 + tid];
            s_R[tid] = s;
        }
        __syncthreads();
    }

    // exchange initial column partials (buf 0)
    #pragma unroll
    for (int c = 0; c < 4; c++) s_colbuf[0][c * 512 + tid] = colsum[c];
    asm volatile("barrier.cluster.arrive.aligned;" ::: "memory");
    asm volatile("barrier.cluster.wait.aligned;" ::: "memory");
    #pragma unroll
    for (int c = 0; c < 4; c++) {
        float pv;
        asm volatile("ld.shared::cluster.f32 %0, [%1];"
                     : "=f"(pv) : "r"(peerColBase + (uint32_t)(c * 512 + tid) * 4u));
        colsum[c] += pv;
    }

    // col_zero smoothing (dead in practice — softplus > 0 — kept for exactness)
    #pragma unroll
    for (int c = 0; c < 4; c++) {
        if (val[c] && colsum[c] <= 0.f && C0[c] > 0.f) {
            #pragma unroll
            for (int g = 0; g < 16; g++) yv[g][c] += 1e-8f;
            colsum[c] += 32.f * 1e-8f;
        }
    }

    for (int it = 0; it < 60; it++) {
        float cf[4];
        #pragma unroll
        for (int c = 0; c < 4; c++)
            cf[c] = fminf(fmaxf(C0[c] / fmaxf(colsum[c], EPSC), 0.75f), 1.25f);
        float rs[16];
        #pragma unroll
        for (int g = 0; g < 16; g++) {
            float s = 0.f;
            #pragma unroll
            for (int c = 0; c < 4; c++) {
                float v = yv[g][c] * cf[c];
                yv[g][c] = v; s += v;
            }
            rs[g] = s;
        }
        {
            float out; int gh;
            warp_reduce16(rs, lane, out, gh);
            if (!(lane & 1)) s_red[warp * 16 + gh] = out;
        }
        __syncthreads();
        if (tid < 16) {
            float s = 0.f;
            #pragma unroll
            for (int w = 0; w < 16; w++) s += s_red[w * 16 + tid];
            s_rowfac[tid] = fminf(fmaxf(s_R[tid] / fmaxf(s, EPSC), 0.75f), 1.25f);
        }
        __syncthreads();
        #pragma unroll
        for (int c = 0; c < 4; c++) colsum[c] = 0.f;
        #pragma unroll
        for (int g = 0; g < 16; g++) {
            float rf = s_rowfac[g];
            #pragma unroll
            for (int c = 0; c < 4; c++) {
                float v = yv[g][c] * rf;
                yv[g][c] = v; colsum[c] += v;
            }
        }
        int buf = (it + 1) & 1;
        #pragma unroll
        for (int c = 0; c < 4; c++) s_colbuf[buf][c * 512 + tid] = colsum[c];
        asm volatile("barrier.cluster.arrive.aligned;" ::: "memory");
        asm volatile("barrier.cluster.wait.aligned;" ::: "memory");
        #pragma unroll
        for (int c = 0; c < 4; c++) {
            float pv;
            asm volatile("ld.shared::cluster.f32 %0, [%1];"
                         : "=f"(pv)
                         : "r"(peerColBase + (uint32_t)(buf * 2048 + c * 512 + tid) * 4u));
            colsum[c] += pv;
        }
    }

    asm volatile("barrier.cluster.arrive.aligned;" ::: "memory");
    asm volatile("barrier.cluster.wait.aligned;" ::: "memory");

    #pragma unroll
    for (int c = 0; c < 4; c++) {
        if (val[c]) {
            float f = C0[c] / fmaxf(colsum[c], EPSC);
            #pragma unroll
            for (int g = 0; g < 16; g++) yg[g * ND + dIdx[c]] = yv[g][c] * f;
        }
    }
}

// ---------------- stage 5: exact integerization (smem-transposed tiles) ----------------
__global__ void k_round(const int* __restrict__ ts, float* __restrict__ out, int off) {
    const unsigned FULL = 0xffffffffu;
    const int b = blockIdx.y;
    const int d0 = blockIdx.x * 64;
    const int tid = threadIdx.x, lane = tid & 31, warp = tid >> 5;
    __shared__ float sy[32 * 65];
    __shared__ int   so[32 * 65];

    #pragma unroll
    for (int i = 0; i < 8; i++) {       // coalesced load of 32g x 64d tile
        int idx = tid + i * 256;
        int row = idx >> 6, col = idx & 63;
        int d = d0 + col;
        sy[row * 65 + col] = (d < ND) ? g_Y[(size_t)(b * NG + row) * ND + d] : 0.f;
    }
    __syncthreads();

    #pragma unroll
    for (int rep = 0; rep < 8; rep++) {
        int dcol = warp * 8 + rep;      // warp-uniform column
        int d = d0 + dcol;
        if (d < ND) {
            float v = fmaxf(sy[lane * 65 + dcol], 0.f);   // lane = g
            float xf = floorf(v);
            int yi = (int)xf;
            float fr = v - xf;
            int t = ts[(size_t)b * ND + d];

            int s = __reduce_add_sync(FULL, yi);
            int need = t - s;
            int pos = need > 0 ? need : 0;
            int q = pos >> 5;
            yi += q;
            int r = pos - (q << 5);
            if (r > 0) {
                int cnt = 0;
                #pragma unroll
                for (int k = 1; k < 32; k++) {
                    int j = (lane + k) & 31;
                    float o = __shfl_sync(FULL, fr, j);
                    cnt += (o > fr) || (o == fr && j < lane);
                }
                if (cnt < r) yi += 1;
            }

            int s2 = __reduce_add_sync(FULL, yi);
            int need2 = t - s2;
            int neg = need2 < 0 ? -need2 : 0;
            neg = neg < s2 ? neg : s2;
            if (neg > 0) {
                int q2 = neg >> 5;
                int yb = yi;
                yi -= q2; if (yi < 0) yi = 0;
                int removed = __reduce_add_sync(FULL, yb - yi);
                int r2 = neg - removed;
                if (r2 > 0) {
                    float fm = (yi > 0) ? fr : __int_as_float(0x7f800000);  // +inf
                    int cnt2 = 0;
                    #pragma unroll
                    for (int k = 1; k < 32; k++) {
                        int j = (lane + k) & 31;
                        float o = __shfl_sync(FULL, fm, j);
                        cnt2 += (o < fm) || (o == fm && j < lane);
                    }
                    if (cnt2 < r2) yi -= 1;
                    if (yi < 0) yi = 0;
                }
            }
            so[lane * 65 + dcol] = yi;
        }
    }
    __syncthreads();

    #pragma unroll
    for (int i = 0; i < 8; i++) {       // coalesced store
        int idx = tid + i * 256;
        int row = idx >> 6, col = idx & 63;
        int d = d0 + col;
        if (d < ND)
            out[(size_t)off + (size_t)(b * NG + row) * ND + d] = (float)so[row * 65 + col];
    }
}

// ---------------- launch (pure kernel launches; no runtime API calls) ----------------
extern "C" void kernel_launch(void* const* d_in, const int* in_sizes, int n_in,
                              void* d_out, int out_size) {
    const float* x      = (const float*)d_in[0];   // [2048,256]
    const float* target = (const float*)d_in[1];   // [64,2000]
    const int*   tsum   = (const int*)  d_in[2];   // [64,2000]
    const float* W      = (const float*)d_in[3];   // [272,2000]
    const float* bias   = (const float*)d_in[4];   // [2000]
    const float* nl     = (const float*)d_in[5];   // [32768,16]
    const float* ns     = (const float*)d_in[6];   // [2048,16]
    float* out = (float*)d_out;

    int off = out_size - NB * NG * ND;             // expected 1 (loss scalar first)
    if (off < 0) off = 0;

    // 1) group reductions
    k_reduce<<<128, 256>>>(x, nl);
    // 2a) sample GEMM with softplus (f32x2 packed math): g_Y[2048,2000]
    k_gemm1<<<dim3(16, 16), 256>>>(x, ns, W, bias);
    // 2b) tiny loss-path GEMM, k-split x4: g_Tp
    k_gemmT<<<dim3(8, 8, 4), 256>>>(W, bias);
    // 3) loss: partials (P rebuilt on the fly) -> per-b combine -> final sum
    k_loss_part<<<dim3(NCH, NB), 256>>>(target, W);
    k_loss_comb<<<NB, 256>>>();
    k_loss_final<<<1, 32>>>(out, off);
    // 4) IPF: register-resident, 2-CTA cluster per b
    k_ipf<<<2 * NB, 512>>>(tsum);
    // 5) exact integer rounding (tiled, coalesced)
    k_round<<<dim3(32, NB), 256>>>(tsum, out, off);
}